// round 5
// baseline (speedup 1.0000x reference)
#include <cuda_runtime.h>

#define SS   64
#define BB   32
#define HID  16
#define EMB  32
#define VV   50257
#define SB   (SS*BB)        // 2048
#define GG   64             // 4*HID gate outputs
#define COMB (EMB+HID)      // 48

// scratch (no allocations allowed)
__device__ float g_X[SB*GG];        // precomputed input-part of gates
__device__ float g_H[SB*2*HID];     // concat_h [sb][32]
__device__ float g_sumexp[SB];

using u64 = unsigned long long;

__device__ __forceinline__ u64 fma2(u64 a, u64 b, u64 c) {
    u64 d; asm("fma.rn.f32x2 %0, %1, %2, %3;" : "=l"(d) : "l"(a), "l"(b), "l"(c));
    return d;
}
__device__ __forceinline__ u64 pack2(float x) {
    u64 d; asm("mov.b64 %0, {%1, %1};" : "=l"(d) : "f"(x));
    return d;
}
__device__ __forceinline__ float2 unpack2(u64 a) {
    float lo, hi; asm("mov.b64 {%0, %1}, %2;" : "=f"(lo), "=f"(hi) : "l"(a));
    return make_float2(lo, hi);
}

// ---------------------------------------------------------------------------
__global__ void k_zero() {
    int i = blockIdx.x * blockDim.x + threadIdx.x;
    if (i < SB) g_sumexp[i] = 0.f;
}

// ---------------------------------------------------------------------------
// K1: X[sb][g] = b_gate[h] + sum_e emb[idx[sb]][e] * W_gate[h][e]
__global__ void k_precompute(const int* __restrict__ idx,
                             const float* __restrict__ emb,
                             const float* __restrict__ Wf, const float* __restrict__ bf,
                             const float* __restrict__ Wi, const float* __restrict__ bi,
                             const float* __restrict__ Wc, const float* __restrict__ bc,
                             const float* __restrict__ Wo, const float* __restrict__ bo) {
    int t = blockIdx.x * blockDim.x + threadIdx.x;
    if (t >= SB * GG) return;
    int g    = t & 63;
    int sb   = t >> 6;
    int gate = g >> 4;
    int hh   = g & 15;
    const float* W  = gate == 0 ? Wf : gate == 1 ? Wi : gate == 2 ? Wc : Wo;
    const float* bb = gate == 0 ? bf : gate == 1 ? bi : gate == 2 ? bc : bo;
    const float* e  = emb + (long long)idx[sb] * EMB;
    const float* w  = W + hh * COMB;
    float acc = bb[hh];
#pragma unroll
    for (int k = 0; k < EMB; k++) acc = fmaf(e[k], w[k], acc);
    g_X[t] = acc;
}

// ---------------------------------------------------------------------------
// K2: bidirectional recurrence. One warp per (direction, batch) sequence.
// X loads for step+1 are prefetched to hide the ~577cyc memory latency behind
// the gate math + shfl chain of the current step.
__global__ void k_recur(const float* __restrict__ Wf, const float* __restrict__ Wi,
                        const float* __restrict__ Wc, const float* __restrict__ Wo,
                        const float* __restrict__ h0, const float* __restrict__ C0) {
    int b   = blockIdx.x & 31;
    int dir = blockIdx.x >> 5;
    int t   = threadIdx.x;          // 0..31
    int hh  = t & 15;
    const float* W0 = (t < 16) ? Wf : Wi;   // sigmoid gates
    const float* W1 = (t < 16) ? Wc : Wo;   // tanh (C~) / sigmoid (o)
    float w0[HID], w1[HID];
#pragma unroll
    for (int k = 0; k < HID; k++) {
        w0[k] = W0[hh * COMB + EMB + k];
        w1[k] = W1[hh * COMB + EMB + k];
    }
    float h = h0[hh];
    float C = C0[hh];

    int s0  = dir ? (SS - 1) : 0;
    int sb0 = s0 * BB + b;
    float nx0 = g_X[sb0 * 64 + t];
    float nx1 = g_X[sb0 * 64 + 32 + t];

    for (int step = 0; step < SS; step++) {
        int s  = dir ? (SS - 1 - step) : step;
        int sb = s * BB + b;
        float acc0 = nx0;
        float acc1 = nx1;
        // prefetch next step's X
        if (step + 1 < SS) {
            int sn  = dir ? (SS - 2 - step) : (step + 1);
            int sbn = sn * BB + b;
            nx0 = g_X[sbn * 64 + t];
            nx1 = g_X[sbn * 64 + 32 + t];
        }
        if (t < 16) g_H[sb * 32 + dir * 16 + t] = h;   // pre-step hidden
#pragma unroll
        for (int k = 0; k < HID; k++) {
            float hk = __shfl_sync(0xffffffffu, h, k);
            acc0 = fmaf(hk, w0[k], acc0);
            acc1 = fmaf(hk, w1[k], acc1);
        }
        float a0 = 1.f / (1.f + __expf(-acc0));                          // f or i
        float a1 = (t < 16) ? tanhf(acc1) : 1.f / (1.f + __expf(-acc1)); // C~ or o
        float iv = __shfl_down_sync(0xffffffffu, a0, 16);
        float ov = __shfl_down_sync(0xffffffffu, a1, 16);
        if (t < 16) {
            C = a0 * C + iv * a1;
            h = ov * tanhf(C);
        }
    }
}

// ---------------------------------------------------------------------------
// K3: 128v x 128sb tile, K=32. W staged PRE-DUPLICATED as u64 {w,w} pairs in
// smem (Wd, v-major, pad 33 -> conflict-free LDS.64); H staged k-major as
// floats (natural sb pairs via LDS.128). Inner loop per k: 8 LDS.64 +
// 2 LDS.128 + 32 FFMA2, zero ALU MOVs.
// phase 0: accumulate sum(exp(logit)); phase 1: recompute, write logit - lse.
#define VT 128
#define ST 128

// dynamic smem layout (51.7 KB > 48 KB static limit)
#define WD_ELEMS (VT * 33)            // u64
#define HS_ELEMS (32 * (ST + 4))      // float
#define SMEM_BYTES (WD_ELEMS * 8 + HS_ELEMS * 4 + VT * 4 + ST * 4)

__global__ __launch_bounds__(256, 2)
void k_logits(const float* __restrict__ Who, const float* __restrict__ bho,
              float* __restrict__ out, int phase) {
    extern __shared__ char smraw[];
    u64*   Wd  = (u64*)smraw;                              // [VT][33]
    float* Hs  = (float*)(smraw + WD_ELEMS * 8);           // [32][ST+4]
    float* bs  = (float*)(smraw + WD_ELEMS * 8 + HS_ELEMS * 4);
    float* lss = bs + VT;

    int tid    = threadIdx.x;
    int vbase  = blockIdx.x * VT;
    int sbbase = blockIdx.y * ST;

    // stage W duplicated (v-major) and H (k-major)
    for (int t = tid; t < VT * 8; t += 256) {
        int row = t >> 3;
        int kq  = (t & 7) * 4;
        int v = vbase + row;
        float4 w = (v < VV) ? *(const float4*)&Who[v * 32 + kq]
                            : make_float4(0.f, 0.f, 0.f, 0.f);
        Wd[row * 33 + kq + 0] = pack2(w.x);
        Wd[row * 33 + kq + 1] = pack2(w.y);
        Wd[row * 33 + kq + 2] = pack2(w.z);
        Wd[row * 33 + kq + 3] = pack2(w.w);
        float4 hv = *(const float4*)&g_H[(sbbase + row) * 32 + kq];
        Hs[(kq + 0) * (ST + 4) + row] = hv.x;
        Hs[(kq + 1) * (ST + 4) + row] = hv.y;
        Hs[(kq + 2) * (ST + 4) + row] = hv.z;
        Hs[(kq + 3) * (ST + 4) + row] = hv.w;
    }
    if (tid < VT) bs[tid] = (vbase + tid < VV) ? bho[vbase + tid] : 0.f;
    if (tid < ST) lss[tid] = phase ? __logf(g_sumexp[sbbase + tid]) : 0.f;
    __syncthreads();

    int tx = tid & 15;
    int ty = tid >> 4;

    u64 acc[8][4];                      // [v(i)][sb-pair(j2)]
#pragma unroll
    for (int i = 0; i < 8; i++) {
        u64 bv = pack2(bs[tx + 16 * i]);
#pragma unroll
        for (int j = 0; j < 4; j++) acc[i][j] = bv;
    }

#pragma unroll 4
    for (int k = 0; k < 32; k++) {
        ulonglong2 ha = *(const ulonglong2*)&Hs[k * (ST + 4) + ty * 4];
        ulonglong2 hb = *(const ulonglong2*)&Hs[k * (ST + 4) + 64 + ty * 4];
        u64 h2[4] = {ha.x, ha.y, hb.x, hb.y};
#pragma unroll
        for (int i = 0; i < 8; i++) {
            u64 wp = Wd[(tx + 16 * i) * 33 + k];
#pragma unroll
            for (int j = 0; j < 4; j++)
                acc[i][j] = fma2(wp, h2[j], acc[i][j]);
        }
    }

    if (phase == 0) {
        float part[8];
#pragma unroll
        for (int j = 0; j < 8; j++) part[j] = 0.f;
#pragma unroll
        for (int i = 0; i < 8; i++) {
            if (vbase + tx + 16 * i < VV) {
#pragma unroll
                for (int j = 0; j < 4; j++) {
                    float2 p = unpack2(acc[i][j]);
                    part[2 * j]     += __expf(p.x);
                    part[2 * j + 1] += __expf(p.y);
                }
            }
        }
#pragma unroll
        for (int j = 0; j < 8; j++) {
#pragma unroll
            for (int off = 1; off < 16; off <<= 1)
                part[j] += __shfl_xor_sync(0xffffffffu, part[j], off);
        }
        if (tx == 0) {
#pragma unroll
            for (int jj = 0; jj < 8; jj++) {
                int sbj = (jj < 4) ? ty * 4 + jj : 64 + ty * 4 + (jj - 4);
                atomicAdd(&g_sumexp[sbbase + sbj], part[jj]);
            }
        }
    } else {
#pragma unroll
        for (int jj = 0; jj < 8; jj++) {
            int sbj = (jj < 4) ? ty * 4 + jj : 64 + ty * 4 + (jj - 4);
            float lse = lss[sbj];
            int j2 = jj >> 1;
            int base = (sbbase + sbj) * VV + vbase;
#pragma unroll
            for (int i = 0; i < 8; i++) {
                int v = tx + 16 * i;
                if (vbase + v < VV) {
                    float2 p = unpack2(acc[i][j2]);
                    out[base + v] = ((jj & 1) ? p.y : p.x) - lse;
                }
            }
        }
    }
}

// ---------------------------------------------------------------------------
extern "C" void kernel_launch(void* const* d_in, const int* in_sizes, int n_in,
                              void* d_out, int out_size) {
    const int*   idx = (const int*)  d_in[0];
    const float* emb = (const float*)d_in[1];
    const float* Wf  = (const float*)d_in[2];
    const float* bf  = (const float*)d_in[3];
    const float* Wi  = (const float*)d_in[4];
    const float* bi  = (const float*)d_in[5];
    const float* Wc  = (const float*)d_in[6];
    const float* bc  = (const float*)d_in[7];
    const float* Wo  = (const float*)d_in[8];
    const float* bo  = (const float*)d_in[9];
    const float* Who = (const float*)d_in[10];
    const float* bho = (const float*)d_in[11];
    const float* h0  = (const float*)d_in[12];
    const float* C0  = (const float*)d_in[13];
    float* out = (float*)d_out;

    static int smem_set = 0;
    if (!smem_set) {
        cudaFuncSetAttribute(k_logits, cudaFuncAttributeMaxDynamicSharedMemorySize,
                             SMEM_BYTES);
        smem_set = 1;
    }

    k_precompute<<<(SB * GG + 255) / 256, 256>>>(idx, emb, Wf, bf, Wi, bi, Wc, bc, Wo, bo);
    k_recur<<<64, 32>>>(Wf, Wi, Wc, Wo, h0, C0);
    k_zero<<<(SB + 255) / 256, 256>>>();

    dim3 grid((VV + VT - 1) / VT, SB / ST);   // 393 x 16
    k_logits<<<grid, 256, SMEM_BYTES>>>(Who, bho, out, 0);
    k_logits<<<grid, 256, SMEM_BYTES>>>(Who, bho, out, 1);
}

// round 6
// speedup vs baseline: 1.0013x; 1.0013x over previous
#include <cuda_runtime.h>
#include <cstdint>

#define SS   64
#define BB   32
#define HID  16
#define EMB  32
#define VV   50257
#define SB   (SS*BB)        // 2048
#define GG   64             // 4*HID gate outputs
#define COMB (EMB+HID)      // 48

// scratch (no allocations allowed)
__device__ float g_X[SB*GG];        // precomputed input-part of gates
__device__ float g_H[SB*2*HID];     // concat_h [sb][32]
__device__ float g_sumexp[SB];

// ---------------------------------------------------------------------------
__device__ __forceinline__ uint32_t to_tf32(float x) {
    uint32_t r; asm("cvt.rna.tf32.f32 %0, %1;" : "=r"(r) : "f"(x));
    return r;
}

__device__ __forceinline__ void mma_tf32(float d[4], const uint32_t a[4],
                                         const uint32_t b[2]) {
    asm volatile(
        "mma.sync.aligned.m16n8k8.row.col.f32.tf32.tf32.f32 "
        "{%0,%1,%2,%3}, {%4,%5,%6,%7}, {%8,%9}, {%0,%1,%2,%3};"
        : "+f"(d[0]), "+f"(d[1]), "+f"(d[2]), "+f"(d[3])
        : "r"(a[0]), "r"(a[1]), "r"(a[2]), "r"(a[3]), "r"(b[0]), "r"(b[1]));
}

// fast exp on the FMA pipe (no MUFU): exp(x)=2^y, y=x*log2e, |x|<=9.
// magic-number round, degree-6 Taylor for 2^f on [-0.5,0.5], rel err ~1e-7.
__device__ __forceinline__ float fexp(float x) {
    float y = x * 1.4426950408889634f;
    float t = y + 12582912.0f;          // 1.5*2^23: round y to nearest int
    float n = t - 12582912.0f;
    float f = y - n;
    float p =             1.5403530e-4f;
    p = fmaf(p, f, 1.3333558e-3f);
    p = fmaf(p, f, 9.6181291e-3f);
    p = fmaf(p, f, 5.5504109e-2f);
    p = fmaf(p, f, 2.4022651e-1f);
    p = fmaf(p, f, 6.9314718e-1f);
    float r = fmaf(p, f, 1.0f);
    int e = (__float_as_int(t) << 23) + 0x3F800000;   // 2^n bits
    return r * __int_as_float(e);
}

// ---------------------------------------------------------------------------
__global__ void k_zero() {
    int i = blockIdx.x * blockDim.x + threadIdx.x;
    if (i < SB) g_sumexp[i] = 0.f;
}

// ---------------------------------------------------------------------------
// K1: X[sb][g] = b_gate[h] + sum_e emb[idx[sb]][e] * W_gate[h][e]
__global__ void k_precompute(const int* __restrict__ idx,
                             const float* __restrict__ emb,
                             const float* __restrict__ Wf, const float* __restrict__ bf,
                             const float* __restrict__ Wi, const float* __restrict__ bi,
                             const float* __restrict__ Wc, const float* __restrict__ bc,
                             const float* __restrict__ Wo, const float* __restrict__ bo) {
    int t = blockIdx.x * blockDim.x + threadIdx.x;
    if (t >= SB * GG) return;
    int g    = t & 63;
    int sb   = t >> 6;
    int gate = g >> 4;
    int hh   = g & 15;
    const float* W  = gate == 0 ? Wf : gate == 1 ? Wi : gate == 2 ? Wc : Wo;
    const float* bb = gate == 0 ? bf : gate == 1 ? bi : gate == 2 ? bc : bo;
    const float* e  = emb + (long long)idx[sb] * EMB;
    const float* w  = W + hh * COMB;
    float acc = bb[hh];
#pragma unroll
    for (int k = 0; k < EMB; k++) acc = fmaf(e[k], w[k], acc);
    g_X[t] = acc;
}

// ---------------------------------------------------------------------------
// K2: bidirectional recurrence, one warp per (direction, batch); X prefetched.
__global__ void k_recur(const float* __restrict__ Wf, const float* __restrict__ Wi,
                        const float* __restrict__ Wc, const float* __restrict__ Wo,
                        const float* __restrict__ h0, const float* __restrict__ C0) {
    int b   = blockIdx.x & 31;
    int dir = blockIdx.x >> 5;
    int t   = threadIdx.x;          // 0..31
    int hh  = t & 15;
    const float* W0 = (t < 16) ? Wf : Wi;   // sigmoid gates
    const float* W1 = (t < 16) ? Wc : Wo;   // tanh (C~) / sigmoid (o)
    float w0[HID], w1[HID];
#pragma unroll
    for (int k = 0; k < HID; k++) {
        w0[k] = W0[hh * COMB + EMB + k];
        w1[k] = W1[hh * COMB + EMB + k];
    }
    float h = h0[hh];
    float C = C0[hh];

    int s0  = dir ? (SS - 1) : 0;
    int sb0 = s0 * BB + b;
    float nx0 = g_X[sb0 * 64 + t];
    float nx1 = g_X[sb0 * 64 + 32 + t];

    for (int step = 0; step < SS; step++) {
        int s  = dir ? (SS - 1 - step) : step;
        int sb = s * BB + b;
        float acc0 = nx0;
        float acc1 = nx1;
        if (step + 1 < SS) {
            int sn  = dir ? (SS - 2 - step) : (step + 1);
            int sbn = sn * BB + b;
            nx0 = g_X[sbn * 64 + t];
            nx1 = g_X[sbn * 64 + 32 + t];
        }
        if (t < 16) g_H[sb * 32 + dir * 16 + t] = h;   // pre-step hidden
#pragma unroll
        for (int k = 0; k < HID; k++) {
            float hk = __shfl_sync(0xffffffffu, h, k);
            acc0 = fmaf(hk, w0[k], acc0);
            acc1 = fmaf(hk, w1[k], acc1);
        }
        float a0 = 1.f / (1.f + __expf(-acc0));                          // f or i
        float a1 = (t < 16) ? tanhf(acc1) : 1.f / (1.f + __expf(-acc1)); // C~ or o
        float iv = __shfl_down_sync(0xffffffffu, a0, 16);
        float ov = __shfl_down_sync(0xffffffffu, a1, 16);
        if (t < 16) {
            C = a0 * C + iv * a1;
            h = ov * tanhf(C);
        }
    }
}

// ---------------------------------------------------------------------------
// K3: tensor-core GEMM. Block 128 thr = 4 warps (2m x 2n). Block tile
// 64sb x 128v, K=32 staged in smem as tf32 (pad 36 -> conflict-free frag LDS).
// Warp tile 32sb x 64v = 2 m16 x 8 n8 tiles, 4 k-steps of m16n8k8.
// phase 0: sum(exp(logit)) via poly-exp (fma pipe) + quad shfl + smem atomics.
// phase 1: recompute, write logit - log(sumexp).
#define N_BLK 128
#define M_BLK 64
#define LDP   36      // padded k-stride (words)

__global__ __launch_bounds__(128)
void k_logits(const float* __restrict__ Who, const float* __restrict__ bho,
              float* __restrict__ out, int phase) {
    __shared__ uint32_t As[M_BLK * LDP];
    __shared__ uint32_t Bs[N_BLK * LDP];
    __shared__ float bs[N_BLK];
    __shared__ float sume[M_BLK];
    __shared__ float lss[M_BLK];

    int tid   = threadIdx.x;
    int lane  = tid & 31;
    int wid   = tid >> 5;
    int warpM = wid & 1;        // 0..1
    int warpN = wid >> 1;       // 0..1
    int gq    = lane >> 2;      // groupID 0..7
    int tg    = lane & 3;       // thread-in-group 0..3

    int vbase  = blockIdx.x * N_BLK;
    int sbbase = blockIdx.y * M_BLK;

    // stage A (H) as tf32
    for (int t = tid; t < M_BLK * 8; t += 128) {
        int row = t >> 3, kq = (t & 7) * 4;
        float4 h = *(const float4*)&g_H[(sbbase + row) * 32 + kq];
        As[row * LDP + kq + 0] = to_tf32(h.x);
        As[row * LDP + kq + 1] = to_tf32(h.y);
        As[row * LDP + kq + 2] = to_tf32(h.z);
        As[row * LDP + kq + 3] = to_tf32(h.w);
    }
    // stage B (Who) as tf32
    for (int t = tid; t < N_BLK * 8; t += 128) {
        int row = t >> 3, kq = (t & 7) * 4;
        int v = vbase + row;
        float4 w = (v < VV) ? *(const float4*)&Who[v * 32 + kq]
                            : make_float4(0.f, 0.f, 0.f, 0.f);
        Bs[row * LDP + kq + 0] = to_tf32(w.x);
        Bs[row * LDP + kq + 1] = to_tf32(w.y);
        Bs[row * LDP + kq + 2] = to_tf32(w.z);
        Bs[row * LDP + kq + 3] = to_tf32(w.w);
    }
    bs[tid] = (vbase + tid < VV) ? bho[vbase + tid] : 0.f;
    if (tid < M_BLK) {
        sume[tid] = 0.f;
        lss[tid]  = phase ? __logf(g_sumexp[sbbase + tid]) : 0.f;
    }
    __syncthreads();

    // accumulators, initialized with bias for their v column
    float acc[2][8][4];
#pragma unroll
    for (int mt = 0; mt < 2; mt++)
#pragma unroll
        for (int nt = 0; nt < 8; nt++)
#pragma unroll
            for (int c = 0; c < 4; c++)
                acc[mt][nt][c] = bs[warpN * 64 + nt * 8 + 2 * tg + (c & 1)];

#pragma unroll
    for (int ks = 0; ks < 4; ks++) {
        int k0 = ks * 8;
        uint32_t a[2][4];
#pragma unroll
        for (int mt = 0; mt < 2; mt++) {
            int r = warpM * 32 + mt * 16 + gq;
            a[mt][0] = As[r * LDP + k0 + tg];
            a[mt][1] = As[(r + 8) * LDP + k0 + tg];
            a[mt][2] = As[r * LDP + k0 + tg + 4];
            a[mt][3] = As[(r + 8) * LDP + k0 + tg + 4];
        }
        uint32_t b[8][2];
#pragma unroll
        for (int nt = 0; nt < 8; nt++) {
            int r = warpN * 64 + nt * 8 + gq;
            b[nt][0] = Bs[r * LDP + k0 + tg];
            b[nt][1] = Bs[r * LDP + k0 + tg + 4];
        }
#pragma unroll
        for (int mt = 0; mt < 2; mt++)
#pragma unroll
            for (int nt = 0; nt < 8; nt++)
                mma_tf32(acc[mt][nt], a[mt], b[nt]);
    }

    if (phase == 0) {
        // rows per thread: warpM*32 + {gq, gq+8, 16+gq, 24+gq}
        float rs[4] = {0.f, 0.f, 0.f, 0.f};
#pragma unroll
        for (int mt = 0; mt < 2; mt++)
#pragma unroll
            for (int nt = 0; nt < 8; nt++)
#pragma unroll
                for (int c = 0; c < 4; c++) {
                    int v = vbase + warpN * 64 + nt * 8 + 2 * tg + (c & 1);
                    if (v < VV)
                        rs[mt * 2 + (c >> 1)] += fexp(acc[mt][nt][c]);
                }
#pragma unroll
        for (int j = 0; j < 4; j++) {
            rs[j] += __shfl_xor_sync(0xffffffffu, rs[j], 1);
            rs[j] += __shfl_xor_sync(0xffffffffu, rs[j], 2);
        }
        if (tg == 0) {
            int r = warpM * 32 + gq;
            atomicAdd(&sume[r],      rs[0]);
            atomicAdd(&sume[r + 8],  rs[1]);
            atomicAdd(&sume[r + 16], rs[2]);
            atomicAdd(&sume[r + 24], rs[3]);
        }
        __syncthreads();
        if (tid < M_BLK) atomicAdd(&g_sumexp[sbbase + tid], sume[tid]);
    } else {
#pragma unroll
        for (int mt = 0; mt < 2; mt++)
#pragma unroll
            for (int c = 0; c < 4; c++) {
                int rloc = warpM * 32 + mt * 16 + ((c >> 1) ? 8 : 0) + gq;
                float lse = lss[rloc];
                long long base = (long long)(sbbase + rloc) * VV;
#pragma unroll
                for (int nt = 0; nt < 8; nt++) {
                    int v = vbase + warpN * 64 + nt * 8 + 2 * tg + (c & 1);
                    if (v < VV) out[base + v] = acc[mt][nt][c] - lse;
                }
            }
    }
}

// ---------------------------------------------------------------------------
extern "C" void kernel_launch(void* const* d_in, const int* in_sizes, int n_in,
                              void* d_out, int out_size) {
    const int*   idx = (const int*)  d_in[0];
    const float* emb = (const float*)d_in[1];
    const float* Wf  = (const float*)d_in[2];
    const float* bf  = (const float*)d_in[3];
    const float* Wi  = (const float*)d_in[4];
    const float* bi  = (const float*)d_in[5];
    const float* Wc  = (const float*)d_in[6];
    const float* bc  = (const float*)d_in[7];
    const float* Wo  = (const float*)d_in[8];
    const float* bo  = (const float*)d_in[9];
    const float* Who = (const float*)d_in[10];
    const float* bho = (const float*)d_in[11];
    const float* h0  = (const float*)d_in[12];
    const float* C0  = (const float*)d_in[13];
    float* out = (float*)d_out;

    k_precompute<<<(SB * GG + 255) / 256, 256>>>(idx, emb, Wf, bf, Wi, bi, Wc, bc, Wo, bo);
    k_recur<<<64, 32>>>(Wf, Wi, Wc, Wo, h0, C0);
    k_zero<<<(SB + 255) / 256, 256>>>();

    dim3 grid((VV + N_BLK - 1) / N_BLK, SB / M_BLK);   // 393 x 32
    k_logits<<<grid, 128>>>(Who, bho, out, 0);
    k_logits<<<grid, 128>>>(Who, bho, out, 1);
}

// round 7
// speedup vs baseline: 1.0209x; 1.0195x over previous
#include <cuda_runtime.h>
#include <cstdint>

#define SS   64
#define BB   32
#define HID  16
#define EMB  32
#define VV   50257
#define VPAD 50304          // 393 * 128
#define SB   (SS*BB)        // 2048
#define GG   64             // 4*HID gate outputs
#define COMB (EMB+HID)      // 48

// scratch (no allocations allowed)
__device__ float    g_X[SB*GG];       // precomputed input-part of gates
__device__ uint32_t g_Ht[SB*2*HID];   // concat_h as tf32 bits [sb][32]
__device__ uint32_t g_Wt[VPAD*32];    // Who as tf32 bits, zero-padded rows
__device__ float    g_sumexp[SB];

// ---------------------------------------------------------------------------
__device__ __forceinline__ uint32_t to_tf32(float x) {
    uint32_t r; asm("cvt.rna.tf32.f32 %0, %1;" : "=r"(r) : "f"(x));
    return r;
}

__device__ __forceinline__ void mma_tf32(float d[4], const uint32_t a[4],
                                         const uint32_t b[2]) {
    asm volatile(
        "mma.sync.aligned.m16n8k8.row.col.f32.tf32.tf32.f32 "
        "{%0,%1,%2,%3}, {%4,%5,%6,%7}, {%8,%9}, {%0,%1,%2,%3};"
        : "+f"(d[0]), "+f"(d[1]), "+f"(d[2]), "+f"(d[3])
        : "r"(a[0]), "r"(a[1]), "r"(a[2]), "r"(a[3]), "r"(b[0]), "r"(b[1]));
}

// fast exp on the FMA pipe (no MUFU): exp(x)=2^y, magic-number round +
// degree-6 poly for 2^f on [-0.5,0.5], rel err ~1e-7. |x| <= ~9 here.
__device__ __forceinline__ float fexp(float x) {
    float y = x * 1.4426950408889634f;
    float t = y + 12582912.0f;          // 1.5*2^23
    float n = t - 12582912.0f;
    float f = y - n;
    float p =             1.5403530e-4f;
    p = fmaf(p, f, 1.3333558e-3f);
    p = fmaf(p, f, 9.6181291e-3f);
    p = fmaf(p, f, 5.5504109e-2f);
    p = fmaf(p, f, 2.4022651e-1f);
    p = fmaf(p, f, 6.9314718e-1f);
    float r = fmaf(p, f, 1.0f);
    int e = (__float_as_int(t) << 23) + 0x3F800000;   // 2^n bits
    return r * __int_as_float(e);
}

// ---------------------------------------------------------------------------
// K0: convert Who -> tf32 once per replay (zero-padding rows >= VV) and
// zero the sum-exp accumulator.
__global__ void k_prep(const float* __restrict__ Who) {
    int t = blockIdx.x * blockDim.x + threadIdx.x;
    if (t < SB) g_sumexp[t] = 0.f;
    if (t >= VPAD * 32) return;
    int v = t >> 5;
    g_Wt[t] = (v < VV) ? to_tf32(Who[t]) : 0u;
}

// ---------------------------------------------------------------------------
// K1: X[sb][g] = b_gate[h] + sum_e emb[idx[sb]][e] * W_gate[h][e]
__global__ void k_precompute(const int* __restrict__ idx,
                             const float* __restrict__ emb,
                             const float* __restrict__ Wf, const float* __restrict__ bf,
                             const float* __restrict__ Wi, const float* __restrict__ bi,
                             const float* __restrict__ Wc, const float* __restrict__ bc,
                             const float* __restrict__ Wo, const float* __restrict__ bo) {
    int t = blockIdx.x * blockDim.x + threadIdx.x;
    if (t >= SB * GG) return;
    int g    = t & 63;
    int sb   = t >> 6;
    int gate = g >> 4;
    int hh   = g & 15;
    const float* W  = gate == 0 ? Wf : gate == 1 ? Wi : gate == 2 ? Wc : Wo;
    const float* bb = gate == 0 ? bf : gate == 1 ? bi : gate == 2 ? bc : bo;
    const float* e  = emb + (long long)idx[sb] * EMB;
    const float* w  = W + hh * COMB;
    float acc = bb[hh];
#pragma unroll
    for (int k = 0; k < EMB; k++) acc = fmaf(e[k], w[k], acc);
    g_X[t] = acc;
}

// ---------------------------------------------------------------------------
// K2: bidirectional recurrence, one warp per (direction, batch); X prefetched.
// Hidden state written directly as tf32 bits for the tensor-core GEMM.
__global__ void k_recur(const float* __restrict__ Wf, const float* __restrict__ Wi,
                        const float* __restrict__ Wc, const float* __restrict__ Wo,
                        const float* __restrict__ h0, const float* __restrict__ C0) {
    int b   = blockIdx.x & 31;
    int dir = blockIdx.x >> 5;
    int t   = threadIdx.x;          // 0..31
    int hh  = t & 15;
    const float* W0 = (t < 16) ? Wf : Wi;   // sigmoid gates
    const float* W1 = (t < 16) ? Wc : Wo;   // tanh (C~) / sigmoid (o)
    float w0[HID], w1[HID];
#pragma unroll
    for (int k = 0; k < HID; k++) {
        w0[k] = W0[hh * COMB + EMB + k];
        w1[k] = W1[hh * COMB + EMB + k];
    }
    float h = h0[hh];
    float C = C0[hh];

    int s0  = dir ? (SS - 1) : 0;
    int sb0 = s0 * BB + b;
    float nx0 = g_X[sb0 * 64 + t];
    float nx1 = g_X[sb0 * 64 + 32 + t];

    for (int step = 0; step < SS; step++) {
        int s  = dir ? (SS - 1 - step) : step;
        int sb = s * BB + b;
        float acc0 = nx0;
        float acc1 = nx1;
        if (step + 1 < SS) {
            int sn  = dir ? (SS - 2 - step) : (step + 1);
            int sbn = sn * BB + b;
            nx0 = g_X[sbn * 64 + t];
            nx1 = g_X[sbn * 64 + 32 + t];
        }
        if (t < 16) g_Ht[sb * 32 + dir * 16 + t] = to_tf32(h);   // pre-step hidden
#pragma unroll
        for (int k = 0; k < HID; k++) {
            float hk = __shfl_sync(0xffffffffu, h, k);
            acc0 = fmaf(hk, w0[k], acc0);
            acc1 = fmaf(hk, w1[k], acc1);
        }
        float a0 = 1.f / (1.f + __expf(-acc0));                          // f or i
        float a1 = (t < 16) ? tanhf(acc1) : 1.f / (1.f + __expf(-acc1)); // C~ or o
        float iv = __shfl_down_sync(0xffffffffu, a0, 16);
        float ov = __shfl_down_sync(0xffffffffu, a1, 16);
        if (t < 16) {
            C = a0 * C + iv * a1;
            h = ov * tanhf(C);
        }
    }
}

// ---------------------------------------------------------------------------
// K3: tensor-core GEMM. Block 256 thr = 8 warps (4m x 2n). Block tile
// 128sb x 128v, K=32 staged as pre-converted tf32 bits (pad 36 ->
// conflict-free frag LDS; staging is pure uint4 copy, zero CVTs).
// Warp tile 32sb x 64v = 2 m16 x 8 n8 tiles, 4 k-steps of m16n8k8.
// phase 0: sum(exp(logit)) via poly-exp (fma pipe) + quad shfl + smem atomics.
// phase 1: recompute, write logit - log(sumexp).
#define N_BLK 128
#define M_BLK 128
#define LDP   36      // padded k-stride (words)

__global__ __launch_bounds__(256)
void k_logits(const float* __restrict__ bho, float* __restrict__ out, int phase) {
    __shared__ uint32_t As[M_BLK * LDP];
    __shared__ uint32_t Bs[N_BLK * LDP];
    __shared__ float bs[N_BLK];
    __shared__ float sume[M_BLK];
    __shared__ float lss[M_BLK];

    int tid   = threadIdx.x;
    int lane  = tid & 31;
    int wid   = tid >> 5;
    int warpM = wid & 3;        // 0..3
    int warpN = wid >> 2;       // 0..1
    int gq    = lane >> 2;      // groupID 0..7
    int tg    = lane & 3;       // thread-in-group 0..3

    int vbase  = blockIdx.x * N_BLK;
    int sbbase = blockIdx.y * M_BLK;

    // stage A (H, tf32 bits) and B (Who, tf32 bits) - plain copies
    for (int t = tid; t < M_BLK * 8; t += 256) {
        int row = t >> 3, kq = (t & 7) * 4;
        uint4 hv = *(const uint4*)&g_Ht[(sbbase + row) * 32 + kq];
        As[row * LDP + kq + 0] = hv.x;
        As[row * LDP + kq + 1] = hv.y;
        As[row * LDP + kq + 2] = hv.z;
        As[row * LDP + kq + 3] = hv.w;
    }
    for (int t = tid; t < N_BLK * 8; t += 256) {
        int row = t >> 3, kq = (t & 7) * 4;
        uint4 wv = *(const uint4*)&g_Wt[(vbase + row) * 32 + kq];
        Bs[row * LDP + kq + 0] = wv.x;
        Bs[row * LDP + kq + 1] = wv.y;
        Bs[row * LDP + kq + 2] = wv.z;
        Bs[row * LDP + kq + 3] = wv.w;
    }
    if (tid < N_BLK) {
        bs[tid] = (vbase + tid < VV) ? bho[vbase + tid] : 0.f;
    } else {
        int i = tid - N_BLK;    // 0..127 covers M_BLK
        sume[i] = 0.f;
        lss[i]  = phase ? __logf(g_sumexp[sbbase + i]) : 0.f;
    }
    __syncthreads();

    // accumulators, initialized with bias for their v column
    float acc[2][8][4];
#pragma unroll
    for (int mt = 0; mt < 2; mt++)
#pragma unroll
        for (int nt = 0; nt < 8; nt++)
#pragma unroll
            for (int c = 0; c < 4; c++)
                acc[mt][nt][c] = bs[warpN * 64 + nt * 8 + 2 * tg + (c & 1)];

#pragma unroll
    for (int ks = 0; ks < 4; ks++) {
        int k0 = ks * 8;
        uint32_t a[2][4];
#pragma unroll
        for (int mt = 0; mt < 2; mt++) {
            int r = warpM * 32 + mt * 16 + gq;
            a[mt][0] = As[r * LDP + k0 + tg];
            a[mt][1] = As[(r + 8) * LDP + k0 + tg];
            a[mt][2] = As[r * LDP + k0 + tg + 4];
            a[mt][3] = As[(r + 8) * LDP + k0 + tg + 4];
        }
        uint32_t b[8][2];
#pragma unroll
        for (int nt = 0; nt < 8; nt++) {
            int r = warpN * 64 + nt * 8 + gq;
            b[nt][0] = Bs[r * LDP + k0 + tg];
            b[nt][1] = Bs[r * LDP + k0 + tg + 4];
        }
#pragma unroll
        for (int mt = 0; mt < 2; mt++)
#pragma unroll
            for (int nt = 0; nt < 8; nt++)
                mma_tf32(acc[mt][nt], a[mt], b[nt]);
    }

    if (phase == 0) {
        // rows per thread: warpM*32 + {gq, gq+8, 16+gq, 24+gq}
        float rs[4] = {0.f, 0.f, 0.f, 0.f};
#pragma unroll
        for (int mt = 0; mt < 2; mt++)
#pragma unroll
            for (int nt = 0; nt < 8; nt++)
#pragma unroll
                for (int c = 0; c < 4; c++) {
                    int v = vbase + warpN * 64 + nt * 8 + 2 * tg + (c & 1);
                    if (v < VV)
                        rs[mt * 2 + (c >> 1)] += fexp(acc[mt][nt][c]);
                }
#pragma unroll
        for (int j = 0; j < 4; j++) {
            rs[j] += __shfl_xor_sync(0xffffffffu, rs[j], 1);
            rs[j] += __shfl_xor_sync(0xffffffffu, rs[j], 2);
        }
        if (tg == 0) {
            int r = warpM * 32 + gq;
            atomicAdd(&sume[r],      rs[0]);
            atomicAdd(&sume[r + 8],  rs[1]);
            atomicAdd(&sume[r + 16], rs[2]);
            atomicAdd(&sume[r + 24], rs[3]);
        }
        __syncthreads();
        if (tid < M_BLK) atomicAdd(&g_sumexp[sbbase + tid], sume[tid]);
    } else {
#pragma unroll
        for (int mt = 0; mt < 2; mt++)
#pragma unroll
            for (int c = 0; c < 4; c++) {
                int rloc = warpM * 32 + mt * 16 + ((c >> 1) ? 8 : 0) + gq;
                float lse = lss[rloc];
                long long base = (long long)(sbbase + rloc) * VV;
#pragma unroll
                for (int nt = 0; nt < 8; nt++) {
                    int v = vbase + warpN * 64 + nt * 8 + 2 * tg + (c & 1);
                    if (v < VV) out[base + v] = acc[mt][nt][c] - lse;
                }
            }
    }
}

// ---------------------------------------------------------------------------
extern "C" void kernel_launch(void* const* d_in, const int* in_sizes, int n_in,
                              void* d_out, int out_size) {
    const int*   idx = (const int*)  d_in[0];
    const float* emb = (const float*)d_in[1];
    const float* Wf  = (const float*)d_in[2];
    const float* bf  = (const float*)d_in[3];
    const float* Wi  = (const float*)d_in[4];
    const float* bi  = (const float*)d_in[5];
    const float* Wc  = (const float*)d_in[6];
    const float* bc  = (const float*)d_in[7];
    const float* Wo  = (const float*)d_in[8];
    const float* bo  = (const float*)d_in[9];
    const float* Who = (const float*)d_in[10];
    const float* bho = (const float*)d_in[11];
    const float* h0  = (const float*)d_in[12];
    const float* C0  = (const float*)d_in[13];
    float* out = (float*)d_out;

    k_prep<<<(VPAD * 32 + 255) / 256, 256>>>(Who);
    k_precompute<<<(SB * GG + 255) / 256, 256>>>(idx, emb, Wf, bf, Wi, bi, Wc, bc, Wo, bo);
    k_recur<<<64, 32>>>(Wf, Wi, Wc, Wo, h0, C0);

    dim3 grid(VPAD / N_BLK, SB / M_BLK);   // 393 x 16
    k_logits<<<grid, 256>>>(bho, out, 0);
    k_logits<<<grid, 256>>>(bho, out, 1);
}

// round 9
// speedup vs baseline: 1.2883x; 1.2619x over previous
#include <cuda_runtime.h>
#include <cuda_bf16.h>
#include <cstdint>

#define SS   64
#define BB   32
#define HID  16
#define EMB  32
#define VV   50257
#define VPAD 50304          // 393 * 128
#define NT_G (VPAD/8)       // 6288 global n8-tiles
#define MT_G (2048/16)      // 128 global m16-tiles
#define SB   (SS*BB)        // 2048
#define GG   64
#define COMB (EMB+HID)      // 48

// scratch (no allocations allowed)
__device__ float g_X[SB*GG];            // input-part of gates
__device__ uint4 g_HtP4[MT_G*32*2];     // A fragments: [m16tile][lane][ks] bf16x8
__device__ uint4 g_WtP4[NT_G*32];       // B fragments: [n8tile][lane] bf16x8 (both ks)
__device__ float g_sumexp[SB];

// ---------------------------------------------------------------------------
__device__ __forceinline__ void mma_bf16(float d[4], const uint32_t a[4],
                                         const uint32_t b[2]) {
    asm volatile(
        "mma.sync.aligned.m16n8k16.row.col.f32.bf16.bf16.f32 "
        "{%0,%1,%2,%3}, {%4,%5,%6,%7}, {%8,%9}, {%0,%1,%2,%3};"
        : "+f"(d[0]), "+f"(d[1]), "+f"(d[2]), "+f"(d[3])
        : "r"(a[0]), "r"(a[1]), "r"(a[2]), "r"(a[3]), "r"(b[0]), "r"(b[1]));
}

// fragment address helpers (bf16-element granularity)
// A element (m,k): m16n8k16 .row A-fragment
__device__ __forceinline__ int a_frag_addr(int m, int k) {
    int mt_g = m >> 4, r = m & 15;
    int gq = r & 7, mh = r >> 3;
    int ks = k >> 4, kk = k & 15;
    int tg = (kk >> 1) & 3, kh = kk >> 3, pr = kk & 1;
    int lane = gq * 4 + tg;
    int w = kh * 2 + mh;                 // a0..a3 word
    return (((mt_g * 32 + lane) * 2 + ks) * 4 + w) * 2 + pr;
}
// B element (v,k): .col B-fragment, uint4 packs [b0ks0,b1ks0,b0ks1,b1ks1]
__device__ __forceinline__ int b_frag_addr(int v, int k) {
    int nt_g = v >> 3, gq = v & 7;
    int ks = k >> 4, kk = k & 15;
    int tg = (kk >> 1) & 3, bh = kk >> 3, pr = kk & 1;
    int lane = gq * 4 + tg;
    int w = ks * 2 + bh;
    return ((nt_g * 32 + lane) * 4 + w) * 2 + pr;
}

// ---------------------------------------------------------------------------
// K0: Who -> bf16 fragments (zero-padded rows), zero sum-exp.
__global__ void k_prep(const float* __restrict__ Who) {
    int t = blockIdx.x * blockDim.x + threadIdx.x;
    if (t < SB) g_sumexp[t] = 0.f;
    if (t >= VPAD * 32) return;
    int v = t >> 5, k = t & 31;
    float val = (v < VV) ? Who[t] : 0.f;
    ((__nv_bfloat16*)g_WtP4)[b_frag_addr(v, k)] = __float2bfloat16_rn(val);
}

// ---------------------------------------------------------------------------
// K1: X[sb][g] = b_gate[h] + sum_e emb[idx[sb]][e] * W_gate[h][e]
__global__ void k_precompute(const int* __restrict__ idx,
                             const float* __restrict__ emb,
                             const float* __restrict__ Wf, const float* __restrict__ bf,
                             const float* __restrict__ Wi, const float* __restrict__ bi,
                             const float* __restrict__ Wc, const float* __restrict__ bc,
                             const float* __restrict__ Wo, const float* __restrict__ bo) {
    int t = blockIdx.x * blockDim.x + threadIdx.x;
    if (t >= SB * GG) return;
    int g    = t & 63;
    int sb   = t >> 6;
    int gate = g >> 4;
    int hh   = g & 15;
    const float* W  = gate == 0 ? Wf : gate == 1 ? Wi : gate == 2 ? Wc : Wo;
    const float* bb = gate == 0 ? bf : gate == 1 ? bi : gate == 2 ? bc : bo;
    const float* e  = emb + (long long)idx[sb] * EMB;
    const float* w  = W + hh * COMB;
    float acc = bb[hh];
#pragma unroll
    for (int k = 0; k < EMB; k++) acc = fmaf(e[k], w[k], acc);
    g_X[t] = acc;
}

// ---------------------------------------------------------------------------
// K2: bidirectional recurrence, one warp per (direction, batch); X prefetched.
// Hidden values land directly in bf16 A-fragment order.
__global__ void k_recur(const float* __restrict__ Wf, const float* __restrict__ Wi,
                        const float* __restrict__ Wc, const float* __restrict__ Wo,
                        const float* __restrict__ h0, const float* __restrict__ C0) {
    int b   = blockIdx.x & 31;
    int dir = blockIdx.x >> 5;
    int t   = threadIdx.x;          // 0..31
    int hh  = t & 15;
    const float* W0 = (t < 16) ? Wf : Wi;
    const float* W1 = (t < 16) ? Wc : Wo;
    float w0[HID], w1[HID];
#pragma unroll
    for (int k = 0; k < HID; k++) {
        w0[k] = W0[hh * COMB + EMB + k];
        w1[k] = W1[hh * COMB + EMB + k];
    }
    float h = h0[hh];
    float C = C0[hh];

    int s0  = dir ? (SS - 1) : 0;
    int sb0 = s0 * BB + b;
    float nx0 = g_X[sb0 * 64 + t];
    float nx1 = g_X[sb0 * 64 + 32 + t];

    for (int step = 0; step < SS; step++) {
        int s  = dir ? (SS - 1 - step) : step;
        int sb = s * BB + b;
        float acc0 = nx0;
        float acc1 = nx1;
        if (step + 1 < SS) {
            int sn  = dir ? (SS - 2 - step) : (step + 1);
            int sbn = sn * BB + b;
            nx0 = g_X[sbn * 64 + t];
            nx1 = g_X[sbn * 64 + 32 + t];
        }
        if (t < 16)   // pre-step hidden, written into A-fragment slot
            ((__nv_bfloat16*)g_HtP4)[a_frag_addr(sb, dir * 16 + hh)] =
                __float2bfloat16_rn(h);
#pragma unroll
        for (int k = 0; k < HID; k++) {
            float hk = __shfl_sync(0xffffffffu, h, k);
            acc0 = fmaf(hk, w0[k], acc0);
            acc1 = fmaf(hk, w1[k], acc1);
        }
        float a0 = 1.f / (1.f + __expf(-acc0));                          // f or i
        float a1 = (t < 16) ? tanhf(acc1) : 1.f / (1.f + __expf(-acc1)); // C~ or o
        float iv = __shfl_down_sync(0xffffffffu, a0, 16);
        float ov = __shfl_down_sync(0xffffffffu, a1, 16);
        if (t < 16) {
            C = a0 * C + iv * a1;
            h = ov * tanhf(C);
        }
    }
}

// ---------------------------------------------------------------------------
// K3: bf16 tensor-core GEMM, fragments loaded DIRECTLY from gmem (no smem
// staging, no LDS). Block 256 thr = 8 warps (4m x 2n), tile 128sb x 128v.
// Per thread: 4+8 LDG.128, 32 MMA (m16n8k16), MUFU-based exp epilogue.
#define N_BLK 128
#define M_BLK 128

__global__ __launch_bounds__(256)
void k_logits(const float* __restrict__ bho, float* __restrict__ out, int phase) {
    __shared__ float sume[M_BLK];

    int tid   = threadIdx.x;
    int lane  = tid & 31;
    int wid   = tid >> 5;
    int warpM = wid & 3;        // 0..3
    int warpN = wid >> 2;       // 0..1
    int gq    = lane >> 2;
    int tg    = lane & 3;

    int vbase  = blockIdx.x * N_BLK;
    int sbbase = blockIdx.y * M_BLK;

    // B fragments: one uint4 per n8 tile
    uint4 Bv[8];
#pragma unroll
    for (int nt = 0; nt < 8; nt++) {
        int nt_g = (vbase >> 3) + warpN * 8 + nt;
        Bv[nt] = g_WtP4[nt_g * 32 + lane];
    }
    // A fragments: two uint4 (ks=0,1) per m16 tile
    uint4 Av[2][2];
#pragma unroll
    for (int mt = 0; mt < 2; mt++) {
        int mt_g = (sbbase >> 4) + warpM * 2 + mt;
        Av[mt][0] = g_HtP4[(mt_g * 32 + lane) * 2 + 0];
        Av[mt][1] = g_HtP4[(mt_g * 32 + lane) * 2 + 1];
    }

    // accumulators init with bias
    float acc[2][8][4];
#pragma unroll
    for (int nt = 0; nt < 8; nt++) {
        int v0 = vbase + warpN * 64 + nt * 8 + 2 * tg;
        float b0 = (v0     < VV) ? bho[v0]     : 0.f;
        float b1 = (v0 + 1 < VV) ? bho[v0 + 1] : 0.f;
#pragma unroll
        for (int mt = 0; mt < 2; mt++) {
            acc[mt][nt][0] = b0; acc[mt][nt][1] = b1;
            acc[mt][nt][2] = b0; acc[mt][nt][3] = b1;
        }
    }

#pragma unroll
    for (int ks = 0; ks < 2; ks++)
#pragma unroll
        for (int mt = 0; mt < 2; mt++) {
            uint32_t a[4] = {Av[mt][ks].x, Av[mt][ks].y, Av[mt][ks].z, Av[mt][ks].w};
#pragma unroll
            for (int nt = 0; nt < 8; nt++) {
                uint32_t b[2];
                if (ks == 0) { b[0] = Bv[nt].x; b[1] = Bv[nt].y; }
                else         { b[0] = Bv[nt].z; b[1] = Bv[nt].w; }
                mma_bf16(acc[mt][nt], a, b);
            }
        }

    if (phase == 0) {
        if (tid < M_BLK) sume[tid] = 0.f;
        __syncthreads();
        float rs[4] = {0.f, 0.f, 0.f, 0.f};
#pragma unroll
        for (int mt = 0; mt < 2; mt++)
#pragma unroll
            for (int nt = 0; nt < 8; nt++)
#pragma unroll
                for (int c = 0; c < 4; c++) {
                    int v = vbase + warpN * 64 + nt * 8 + 2 * tg + (c & 1);
                    if (v < VV)
                        rs[mt * 2 + (c >> 1)] += __expf(acc[mt][nt][c]);
                }
#pragma unroll
        for (int j = 0; j < 4; j++) {
            rs[j] += __shfl_xor_sync(0xffffffffu, rs[j], 1);
            rs[j] += __shfl_xor_sync(0xffffffffu, rs[j], 2);
        }
        if (tg == 0) {
            int r = warpM * 32 + gq;
            atomicAdd(&sume[r],      rs[0]);
            atomicAdd(&sume[r + 8],  rs[1]);
            atomicAdd(&sume[r + 16], rs[2]);
            atomicAdd(&sume[r + 24], rs[3]);
        }
        __syncthreads();
        if (tid < M_BLK) atomicAdd(&g_sumexp[sbbase + tid], sume[tid]);
    } else {
#pragma unroll
        for (int mt = 0; mt < 2; mt++)
#pragma unroll
            for (int ch = 0; ch < 2; ch++) {
                int rloc = warpM * 32 + mt * 16 + ch * 8 + gq;
                float lse = __logf(g_sumexp[sbbase + rloc]);
                long long base = (long long)(sbbase + rloc) * VV;
#pragma unroll
                for (int nt = 0; nt < 8; nt++) {
                    int v = vbase + warpN * 64 + nt * 8 + 2 * tg;
                    if (v < VV)     out[base + v]     = acc[mt][nt][2 * ch]     - lse;
                    if (v + 1 < VV) out[base + v + 1] = acc[mt][nt][2 * ch + 1] - lse;
                }
            }
    }
}

// ---------------------------------------------------------------------------
extern "C" void kernel_launch(void* const* d_in, const int* in_sizes, int n_in,
                              void* d_out, int out_size) {
    const int*   idx = (const int*)  d_in[0];
    const float* emb = (const float*)d_in[1];
    const float* Wf  = (const float*)d_in[2];
    const float* bf  = (const float*)d_in[3];
    const float* Wi  = (const float*)d_in[4];
    const float* bi  = (const float*)d_in[5];
    const float* Wc  = (const float*)d_in[6];
    const float* bc  = (const float*)d_in[7];
    const float* Wo  = (const float*)d_in[8];
    const float* bo  = (const float*)d_in[9];
    const float* Who = (const float*)d_in[10];
    const float* bho = (const float*)d_in[11];
    const float* h0  = (const float*)d_in[12];
    const float* C0  = (const float*)d_in[13];
    float* out = (float*)d_out;

    k_prep<<<(VPAD * 32 + 255) / 256, 256>>>(Who);
    k_precompute<<<(SB * GG + 255) / 256, 256>>>(idx, emb, Wf, bf, Wi, bi, Wc, bc, Wo, bo);
    k_recur<<<64, 32>>>(Wf, Wi, Wc, Wo, h0, C0);

    dim3 grid(VPAD / N_BLK, SB / M_BLK);   // 393 x 16
    k_logits<<<grid, 256>>>(bho, out, 0);
    k_logits<<<grid, 256>>>(bho, out, 1);
}

// round 15
// speedup vs baseline: 1.4012x; 1.0877x over previous
#include <cuda_runtime.h>
#include <cuda_bf16.h>
#include <cstdint>

#define SS   64
#define BB   32
#define HID  16
#define EMB  32
#define VV   50257
#define VPAD 50304          // 393 * 128
#define NT_G (VPAD/8)       // 6288 global n8-tiles
#define MT_G (2048/16)      // 128 global m16-tiles
#define SB   (SS*BB)        // 2048
#define GG   64
#define COMB (EMB+HID)      // 48

// scratch (no allocations allowed)
__device__ float g_X[SB*GG];            // input-part of gates
__device__ uint4 g_HtP4[MT_G*32*2];     // A fragments: [m16tile][lane][ks] bf16x8
__device__ uint4 g_WtP4[NT_G*32];       // B fragments: [n8tile][lane] bf16x8 (both ks)
__device__ float g_bpad[VPAD];          // bias, padded with -100 (exp -> 0)
__device__ float g_sumexp[SB];

// ---------------------------------------------------------------------------
__device__ __forceinline__ void mma_bf16(float d[4], const uint32_t a[4],
                                         const uint32_t b[2]) {
    asm volatile(
        "mma.sync.aligned.m16n8k16.row.col.f32.bf16.bf16.f32 "
        "{%0,%1,%2,%3}, {%4,%5,%6,%7}, {%8,%9}, {%0,%1,%2,%3};"
        : "+f"(d[0]), "+f"(d[1]), "+f"(d[2]), "+f"(d[3])
        : "r"(a[0]), "r"(a[1]), "r"(a[2]), "r"(a[3]), "r"(b[0]), "r"(b[1]));
}

// A element (m,k) -> bf16 slot in g_HtP4 (used by k_recur's scatter; tiny volume)
__device__ __forceinline__ int a_frag_addr(int m, int k) {
    int mt_g = m >> 4, r = m & 15;
    int gq = r & 7, mh = r >> 3;
    int ks = k >> 4, kk = k & 15;
    int tg = (kk >> 1) & 3, kh = kk >> 3, pr = kk & 1;
    int lane = gq * 4 + tg;
    int w = kh * 2 + mh;
    return (((mt_g * 32 + lane) * 2 + ks) * 4 + w) * 2 + pr;
}

// ---------------------------------------------------------------------------
// K0: Who -> bf16 B-fragments, fully coalesced: thread = (n8tile, lane),
// builds its uint4 fragment from 4 LDG.64 and writes one 16B store.
// Word w holds k = 16*(w>>1) + 8*(w&1) + tg*2 + {0,1}; v = nt*8 + gq.
// Also: padded bias (-100 beyond VV) and sum-exp zeroing.
__global__ void k_prep(const float* __restrict__ Who, const float* __restrict__ bho) {
    int t = blockIdx.x * blockDim.x + threadIdx.x;
    if (t < SB) g_sumexp[t] = 0.f;
    if (t < VPAD) g_bpad[t] = (t < VV) ? bho[t] : -100.f;
    if (t >= NT_G * 32) return;
    int lane = t & 31, nt_g = t >> 5;
    int gq = lane >> 2, tg = lane & 3;
    int v = nt_g * 8 + gq;
    uint32_t wds[4] = {0u, 0u, 0u, 0u};
    if (v < VV) {
        const float* row = Who + v * 32;
#pragma unroll
        for (int w = 0; w < 4; w++) {
            int k0 = 16 * (w >> 1) + 8 * (w & 1) + tg * 2;
            float2 f = *(const float2*)&row[k0];
            __nv_bfloat162 h2 = __floats2bfloat162_rn(f.x, f.y);
            wds[w] = *(uint32_t*)&h2;
        }
    }
    g_WtP4[t] = make_uint4(wds[0], wds[1], wds[2], wds[3]);
}

// ---------------------------------------------------------------------------
// K1: X[sb][g] = b_gate[h] + sum_e emb[idx[sb]][e] * W_gate[h][e]
__global__ void k_precompute(const int* __restrict__ idx,
                             const float* __restrict__ emb,
                             const float* __restrict__ Wf, const float* __restrict__ bf,
                             const float* __restrict__ Wi, const float* __restrict__ bi,
                             const float* __restrict__ Wc, const float* __restrict__ bc,
                             const float* __restrict__ Wo, const float* __restrict__ bo) {
    int t = blockIdx.x * blockDim.x + threadIdx.x;
    if (t >= SB * GG) return;
    int g    = t & 63;
    int sb   = t >> 6;
    int gate = g >> 4;
    int hh   = g & 15;
    const float* W  = gate == 0 ? Wf : gate == 1 ? Wi : gate == 2 ? Wc : Wo;
    const float* bb = gate == 0 ? bf : gate == 1 ? bi : gate == 2 ? bc : bo;
    const float* e  = emb + (long long)idx[sb] * EMB;
    const float* w  = W + hh * COMB;
    float acc = bb[hh];
#pragma unroll
    for (int k = 0; k < EMB; k++) acc = fmaf(e[k], w[k], acc);
    g_X[t] = acc;
}

// ---------------------------------------------------------------------------
// K2: bidirectional recurrence, one warp per (direction, batch); X prefetched.
// Hidden values land directly in bf16 A-fragment order (small scatter, OK).
__global__ void k_recur(const float* __restrict__ Wf, const float* __restrict__ Wi,
                        const float* __restrict__ Wc, const float* __restrict__ Wo,
                        const float* __restrict__ h0, const float* __restrict__ C0) {
    int b   = blockIdx.x & 31;
    int dir = blockIdx.x >> 5;
    int t   = threadIdx.x;          // 0..31
    int hh  = t & 15;
    const float* W0 = (t < 16) ? Wf : Wi;
    const float* W1 = (t < 16) ? Wc : Wo;
    float w0[HID], w1[HID];
#pragma unroll
    for (int k = 0; k < HID; k++) {
        w0[k] = W0[hh * COMB + EMB + k];
        w1[k] = W1[hh * COMB + EMB + k];
    }
    float h = h0[hh];
    float C = C0[hh];

    int s0  = dir ? (SS - 1) : 0;
    int sb0 = s0 * BB + b;
    float nx0 = g_X[sb0 * 64 + t];
    float nx1 = g_X[sb0 * 64 + 32 + t];

    for (int step = 0; step < SS; step++) {
        int s  = dir ? (SS - 1 - step) : step;
        int sb = s * BB + b;
        float acc0 = nx0;
        float acc1 = nx1;
        if (step + 1 < SS) {
            int sn  = dir ? (SS - 2 - step) : (step + 1);
            int sbn = sn * BB + b;
            nx0 = g_X[sbn * 64 + t];
            nx1 = g_X[sbn * 64 + 32 + t];
        }
        if (t < 16)
            ((__nv_bfloat16*)g_HtP4)[a_frag_addr(sb, dir * 16 + hh)] =
                __float2bfloat16_rn(h);
#pragma unroll
        for (int k = 0; k < HID; k++) {
            float hk = __shfl_sync(0xffffffffu, h, k);
            acc0 = fmaf(hk, w0[k], acc0);
            acc1 = fmaf(hk, w1[k], acc1);
        }
        float a0 = 1.f / (1.f + __expf(-acc0));                          // f or i
        float a1 = (t < 16) ? tanhf(acc1) : 1.f / (1.f + __expf(-acc1)); // C~ or o
        float iv = __shfl_down_sync(0xffffffffu, a0, 16);
        float ov = __shfl_down_sync(0xffffffffu, a1, 16);
        if (t < 16) {
            C = a0 * C + iv * a1;
            h = ov * tanhf(C);
        }
    }
}

// ---------------------------------------------------------------------------
// K3: bf16 tensor-core GEMM, fragments loaded DIRECTLY from gmem. Block
// 256 thr = 8 warps (4m x 2n), tile 128sb x 128v. Padded bias (-100) makes
// the phase-0 exp epilogue guard-free; phase-1 guards only in the tail block.
#define N_BLK 128
#define M_BLK 128

__global__ __launch_bounds__(256)
void k_logits(float* __restrict__ out, int phase) {
    __shared__ float sume[M_BLK];

    int tid   = threadIdx.x;
    int lane  = tid & 31;
    int wid   = tid >> 5;
    int warpM = wid & 3;        // 0..3
    int warpN = wid >> 2;       // 0..1
    int gq    = lane >> 2;
    int tg    = lane & 3;

    int vbase  = blockIdx.x * N_BLK;
    int sbbase = blockIdx.y * M_BLK;

    // B fragments: one uint4 per n8 tile
    uint4 Bv[8];
#pragma unroll
    for (int nt = 0; nt < 8; nt++) {
        int nt_g = (vbase >> 3) + warpN * 8 + nt;
        Bv[nt] = g_WtP4[nt_g * 32 + lane];
    }
    // A fragments: two uint4 (ks=0,1) per m16 tile
    uint4 Av[2][2];
#pragma unroll
    for (int mt = 0; mt < 2; mt++) {
        int mt_g = (sbbase >> 4) + warpM * 2 + mt;
        Av[mt][0] = g_HtP4[(mt_g * 32 + lane) * 2 + 0];
        Av[mt][1] = g_HtP4[(mt_g * 32 + lane) * 2 + 1];
    }

    // accumulators init with padded bias (guard-free)
    float acc[2][8][4];
#pragma unroll
    for (int nt = 0; nt < 8; nt++) {
        int v0 = vbase + warpN * 64 + nt * 8 + 2 * tg;
        float2 b01 = *(const float2*)&g_bpad[v0];
#pragma unroll
        for (int mt = 0; mt < 2; mt++) {
            acc[mt][nt][0] = b01.x; acc[mt][nt][1] = b01.y;
            acc[mt][nt][2] = b01.x; acc[mt][nt][3] = b01.y;
        }
    }

#pragma unroll
    for (int ks = 0; ks < 2; ks++)
#pragma unroll
        for (int mt = 0; mt < 2; mt++) {
            uint32_t a[4] = {Av[mt][ks].x, Av[mt][ks].y, Av[mt][ks].z, Av[mt][ks].w};
#pragma unroll
            for (int nt = 0; nt < 8; nt++) {
                uint32_t b[2];
                if (ks == 0) { b[0] = Bv[nt].x; b[1] = Bv[nt].y; }
                else         { b[0] = Bv[nt].z; b[1] = Bv[nt].w; }
                mma_bf16(acc[mt][nt], a, b);
            }
        }

    if (phase == 0) {
        if (tid < M_BLK) sume[tid] = 0.f;
        __syncthreads();
        float rs[4] = {0.f, 0.f, 0.f, 0.f};
#pragma unroll
        for (int mt = 0; mt < 2; mt++)
#pragma unroll
            for (int nt = 0; nt < 8; nt++)
#pragma unroll
                for (int c = 0; c < 4; c++)
                    rs[mt * 2 + (c >> 1)] += __expf(acc[mt][nt][c]);
#pragma unroll
        for (int j = 0; j < 4; j++) {
            rs[j] += __shfl_xor_sync(0xffffffffu, rs[j], 1);
            rs[j] += __shfl_xor_sync(0xffffffffu, rs[j], 2);
        }
        if (tg == 0) {
            int r = warpM * 32 + gq;
            atomicAdd(&sume[r],      rs[0]);
            atomicAdd(&sume[r + 8],  rs[1]);
            atomicAdd(&sume[r + 16], rs[2]);
            atomicAdd(&sume[r + 24], rs[3]);
        }
        __syncthreads();
        if (tid < M_BLK) atomicAdd(&g_sumexp[sbbase + tid], sume[tid]);
    } else {
        bool full = (vbase + N_BLK <= VV);   // uniform across block
#pragma unroll
        for (int mt = 0; mt < 2; mt++)
#pragma unroll
            for (int ch = 0; ch < 2; ch++) {
                int rloc = warpM * 32 + mt * 16 + ch * 8 + gq;
                float lse = __logf(g_sumexp[sbbase + rloc]);
                long long base = (long long)(sbbase + rloc) * VV;
                if (full) {
#pragma unroll
                    for (int nt = 0; nt < 8; nt++) {
                        int v = vbase + warpN * 64 + nt * 8 + 2 * tg;
                        out[base + v]     = acc[mt][nt][2 * ch]     - lse;
                        out[base + v + 1] = acc[mt][nt][2 * ch + 1] - lse;
                    }
                } else {
#pragma unroll
                    for (int nt = 0; nt < 8; nt++) {
                        int v = vbase + warpN * 64 + nt * 8 + 2 * tg;
                        if (v < VV)     out[base + v]     = acc[mt][nt][2 * ch]     - lse;
                        if (v + 1 < VV) out[base + v + 1] = acc[mt][nt][2 * ch + 1] - lse;
                    }
                }
            }
    }
}

// ---------------------------------------------------------------------------
extern "C" void kernel_launch(void* const* d_in, const int* in_sizes, int n_in,
                              void* d_out, int out_size) {
    const int*   idx = (const int*)  d_in[0];
    const float* emb = (const float*)d_in[1];
    const float* Wf  = (const float*)d_in[2];
    const float* bf  = (const float*)d_in[3];
    const float* Wi  = (const float*)d_in[4];
    const float* bi  = (const float*)d_in[5];
    const float* Wc  = (const float*)d_in[6];
    const float* bc  = (const float*)d_in[7];
    const float* Wo  = (const float*)d_in[8];
    const float* bo  = (const float*)d_in[9];
    const float* Who = (const float*)d_in[10];
    const float* bho = (const float*)d_in[11];
    const float* h0  = (const float*)d_in[12];
    const float* C0  = (const float*)d_in[13];
    float* out = (float*)d_out;

    k_prep<<<(NT_G * 32 + 255) / 256, 256>>>(Who, bho);
    k_precompute<<<(SB * GG + 255) / 256, 256>>>(idx, emb, Wf, bf, Wi, bi, Wc, bc, Wo, bo);
    k_recur<<<64, 32>>>(Wf, Wi, Wc, Wo, h0, C0);

    dim3 grid(VPAD / N_BLK, SB / M_BLK);   // 393 x 16
    k_logits<<<grid, 256>>>(out, 0);
    k_logits<<<grid, 256>>>(out, 1);
}